// round 1
// baseline (speedup 1.0000x reference)
#include <cuda_runtime.h>

// ----------------------------------------------------------------------------
// Self_Attention: out = softmax(Q K^T) * (1/sqrt(Dk)) @ V
//   Q = x Wq^T + bq ; K = x Wk^T + bk ; V = x Wv^T + bv
// Shapes: x [B=4, S=2048, Din=1024], W* [1024, 1024], out [4, 2048, 1024] fp32
// Round 0: pure fp32 register-blocked GEMMs (128x128x16 tiles, 8x8 per thread)
// ----------------------------------------------------------------------------

#define BB 4
#define SS 2048
#define DIN 1024
#define DK 1024
#define DV 1024

// Scratch (device globals: allocation-free per harness rules)
__device__ float g_Q[BB * SS * DK];      // 32 MB
__device__ float g_K[BB * SS * DK];      // 32 MB
__device__ float g_V[BB * SS * DV];      // 32 MB
__device__ float g_S[BB * SS * SS];      // 64 MB (scores / attention probs)

#define BM 128
#define BN 128
#define BKT 16

// C[M,N] = A[M,K] @ op(B) + bias
//   BT=true : B is [N,K] row-major (NT gemm, torch-Linear weight layout)
//   BT=false: B is [K,N] row-major (NN gemm)
// blockIdx.z = batch; strides are element strides per batch.
template <bool BT, bool HAS_BIAS>
__global__ __launch_bounds__(256, 2)
void gemm_128(const float* __restrict__ A, const float* __restrict__ Bp,
              const float* __restrict__ bias, float* __restrict__ C,
              int M, int N, int K,
              long strideA, long strideB, long strideC)
{
    __shared__ float As[BKT][BM];
    __shared__ float Bs[BKT][BN];

    const long bz = blockIdx.z;
    A  += bz * strideA;
    Bp += bz * strideB;
    C  += bz * strideC;

    const int m0 = blockIdx.y * BM;
    const int n0 = blockIdx.x * BN;
    const int tid = threadIdx.x;
    const int tx = tid & 15;   // 0..15 -> col groups
    const int ty = tid >> 4;   // 0..15 -> row groups

    float acc[8][8];
#pragma unroll
    for (int i = 0; i < 8; i++)
#pragma unroll
        for (int j = 0; j < 8; j++) acc[i][j] = 0.0f;

    for (int kt = 0; kt < K; kt += BKT) {
        // ---- load A tile [BM x BKT], store transposed As[k][m] ----
#pragma unroll
        for (int l = 0; l < 2; l++) {
            int f = tid + l * 256;          // float4 id, 512 total
            int row = f >> 2;               // 0..127
            int kq = (f & 3) << 2;          // 0,4,8,12
            float4 a = *(const float4*)(A + (long)(m0 + row) * K + kt + kq);
            As[kq + 0][row] = a.x;
            As[kq + 1][row] = a.y;
            As[kq + 2][row] = a.z;
            As[kq + 3][row] = a.w;
        }
        // ---- load B tile ----
        if (BT) {
            // B [N,K]: rows n0..n0+127, cols kt..kt+15 -> Bs[k][n]
#pragma unroll
            for (int l = 0; l < 2; l++) {
                int f = tid + l * 256;
                int row = f >> 2;           // n offset 0..127
                int kq = (f & 3) << 2;
                float4 b = *(const float4*)(Bp + (long)(n0 + row) * K + kt + kq);
                Bs[kq + 0][row] = b.x;
                Bs[kq + 1][row] = b.y;
                Bs[kq + 2][row] = b.z;
                Bs[kq + 3][row] = b.w;
            }
        } else {
            // B [K,N]: rows kt..kt+15, cols n0..n0+127 -> Bs[k][n] direct
#pragma unroll
            for (int l = 0; l < 2; l++) {
                int f = tid + l * 256;
                int krow = f >> 5;          // 0..15
                int nq = (f & 31) << 2;     // 0..124
                float4 b = *(const float4*)(Bp + (long)(kt + krow) * N + n0 + nq);
                *(float4*)&Bs[krow][nq] = b;
            }
        }
        __syncthreads();

        // ---- compute 8x8 per thread ----
#pragma unroll
        for (int k = 0; k < BKT; k++) {
            float4 a0 = *(const float4*)&As[k][ty * 4];
            float4 a1 = *(const float4*)&As[k][ty * 4 + 64];
            float4 b0 = *(const float4*)&Bs[k][tx * 4];
            float4 b1 = *(const float4*)&Bs[k][tx * 4 + 64];
            float ra[8] = {a0.x, a0.y, a0.z, a0.w, a1.x, a1.y, a1.z, a1.w};
            float rb[8] = {b0.x, b0.y, b0.z, b0.w, b1.x, b1.y, b1.z, b1.w};
#pragma unroll
            for (int i = 0; i < 8; i++)
#pragma unroll
                for (int j = 0; j < 8; j++)
                    acc[i][j] = fmaf(ra[i], rb[j], acc[i][j]);
        }
        __syncthreads();
    }

    // ---- epilogue ----
    float4 bb0 = make_float4(0.f, 0.f, 0.f, 0.f);
    float4 bb1 = make_float4(0.f, 0.f, 0.f, 0.f);
    if (HAS_BIAS) {
        bb0 = *(const float4*)(bias + n0 + tx * 4);
        bb1 = *(const float4*)(bias + n0 + 64 + tx * 4);
    }
#pragma unroll
    for (int i = 0; i < 8; i++) {
        int rm = m0 + ty * 4 + ((i < 4) ? i : (64 + i - 4));
        float4 c0, c1;
        c0.x = acc[i][0] + bb0.x; c0.y = acc[i][1] + bb0.y;
        c0.z = acc[i][2] + bb0.z; c0.w = acc[i][3] + bb0.w;
        c1.x = acc[i][4] + bb1.x; c1.y = acc[i][5] + bb1.y;
        c1.z = acc[i][6] + bb1.z; c1.w = acc[i][7] + bb1.w;
        *(float4*)(C + (long)rm * N + n0 + tx * 4)      = c0;
        *(float4*)(C + (long)rm * N + n0 + 64 + tx * 4) = c1;
    }
}

// ---------------- softmax over rows of [rows, 2048], scaled ----------------
__inline__ __device__ float warpReduceMax(float v) {
#pragma unroll
    for (int o = 16; o > 0; o >>= 1) v = fmaxf(v, __shfl_xor_sync(0xffffffffu, v, o));
    return v;
}
__inline__ __device__ float warpReduceSum(float v) {
#pragma unroll
    for (int o = 16; o > 0; o >>= 1) v += __shfl_xor_sync(0xffffffffu, v, o);
    return v;
}

__global__ __launch_bounds__(256)
void softmax_rows_2048(float* __restrict__ Sc, float scale)
{
    __shared__ float red[8];
    const long row = blockIdx.x;
    float* p = Sc + row * 2048;
    const int tid = threadIdx.x;
    const int lane = tid & 31;
    const int wid = tid >> 5;

    float v[8];
#pragma unroll
    for (int i = 0; i < 8; i++) v[i] = p[tid + i * 256];

    float m = -1e30f;
#pragma unroll
    for (int i = 0; i < 8; i++) m = fmaxf(m, v[i]);
    m = warpReduceMax(m);
    if (lane == 0) red[wid] = m;
    __syncthreads();
    if (tid < 32) {
        float t = (lane < 8) ? red[lane] : -1e30f;
        t = warpReduceMax(t);
        if (lane == 0) red[0] = t;
    }
    __syncthreads();
    m = red[0];
    __syncthreads();

    float s = 0.0f;
#pragma unroll
    for (int i = 0; i < 8; i++) { v[i] = __expf(v[i] - m); s += v[i]; }
    s = warpReduceSum(s);
    if (lane == 0) red[wid] = s;
    __syncthreads();
    if (tid < 32) {
        float t = (lane < 8) ? red[lane] : 0.0f;
        t = warpReduceSum(t);
        if (lane == 0) red[0] = t;
    }
    __syncthreads();
    s = red[0];

    float r = scale / s;
#pragma unroll
    for (int i = 0; i < 8; i++) p[tid + i * 256] = v[i] * r;
}

// ---------------------------------------------------------------------------
extern "C" void kernel_launch(void* const* d_in, const int* in_sizes, int n_in,
                              void* d_out, int out_size)
{
    const float* x  = (const float*)d_in[0];
    const float* Wq = (const float*)d_in[1];
    const float* bq = (const float*)d_in[2];
    const float* Wk = (const float*)d_in[3];
    const float* bk = (const float*)d_in[4];
    const float* Wv = (const float*)d_in[5];
    const float* bv = (const float*)d_in[6];
    float* out = (float*)d_out;

    float *Qp, *Kp, *Vp, *Sp;
    cudaGetSymbolAddress((void**)&Qp, g_Q);
    cudaGetSymbolAddress((void**)&Kp, g_K);
    cudaGetSymbolAddress((void**)&Vp, g_V);
    cudaGetSymbolAddress((void**)&Sp, g_S);

    dim3 blk(256);

    // QKV projections: [8192,1024] = x[8192,1024] @ W^T[1024,1024] + b
    {
        dim3 g(DK / BN, (BB * SS) / BM, 1);
        gemm_128<true, true><<<g, blk>>>(x, Wq, bq, Qp, BB * SS, DK, DIN, 0, 0, 0);
        gemm_128<true, true><<<g, blk>>>(x, Wk, bk, Kp, BB * SS, DK, DIN, 0, 0, 0);
        gemm_128<true, true><<<g, blk>>>(x, Wv, bv, Vp, BB * SS, DV, DIN, 0, 0, 0);
    }

    // Scores: per-batch S[q,s] = Q[q,:] . K[s,:]   (NT gemm, batched via z)
    {
        dim3 g(SS / BN, SS / BM, BB);
        gemm_128<true, false><<<g, blk>>>(Qp, Kp, nullptr, Sp,
                                          SS, SS, DK,
                                          (long)SS * DK, (long)SS * DK, (long)SS * SS);
    }

    // Softmax over last dim, then * 1/sqrt(Dk)  (faithful to reference order)
    softmax_rows_2048<<<BB * SS, blk>>>(Sp, 0.03125f);

    // Output: per-batch out[q,v] = A[q,:] @ V[:,v]   (NN gemm, batched via z)
    {
        dim3 g(DV / BN, SS / BM, BB);
        gemm_128<false, false><<<g, blk>>>(Sp, Vp, nullptr, out,
                                           SS, DV, SS,
                                           (long)SS * SS, (long)SS * DV, (long)SS * DV);
    }
}

// round 4
// speedup vs baseline: 2.7113x; 2.7113x over previous
#include <cuda_runtime.h>
#include <cuda_bf16.h>
#include <cstdint>

// ============================================================================
// Self_Attention on GB300 (sm_103a), Round 4: mma.sync bf16x3 GEMMs
//   (R3 bug: scores GEMM used K3=6144 against 3072-wide split buffers -> OOB
//    reads decoded as bf16 NaN patterns. Fixed: K3 = 3*DD = 3072.)
//   Q = x Wq^T + bq ; K = x Wk^T + bk ; V = x Wv^T + bv
//   out = (softmax(Q K^T) / sqrt(Dk)) @ V
// Error-compensated bf16: A' = [Ah|Al|Ah], B' = [Bh|Bh|Bl], K' = 3K
//   -> Ah.Bh + Al.Bh + Ah.Bl  (drops Al.Bl ~ 2^-18 relative)
// ============================================================================

#define BB 4
#define SS 2048
#define DD 1024

// ---------------------------------------------------------------------------
// Scratch pool (device global; allocation-free per harness rules)
// ---------------------------------------------------------------------------
constexpr size_t SZ_X3  = (size_t)BB * SS * 3 * DD * 2;     // 48 MB bf16
constexpr size_t SZ_W3  = (size_t)DD * 3 * DD * 2;          // 6 MB bf16
constexpr size_t SZ_QF  = (size_t)BB * SS * DD * 4;         // 32 MB fp32
constexpr size_t SZ_Q3  = (size_t)BB * SS * 3 * DD * 2;     // 48 MB bf16
constexpr size_t SZ_S   = (size_t)BB * SS * SS * 4;         // 64 MB fp32
constexpr size_t SZ_S3  = (size_t)BB * SS * 3 * SS * 2;     // 96 MB bf16
constexpr size_t SZ_VT3 = (size_t)BB * DD * 3 * SS * 2;     // 48 MB bf16

constexpr size_t OFF_X3  = 0;
constexpr size_t OFF_WQ3 = OFF_X3  + SZ_X3;
constexpr size_t OFF_WK3 = OFF_WQ3 + SZ_W3;
constexpr size_t OFF_WV3 = OFF_WK3 + SZ_W3;
constexpr size_t OFF_QF  = OFF_WV3 + SZ_W3;
constexpr size_t OFF_KF  = OFF_QF  + SZ_QF;
constexpr size_t OFF_VT  = OFF_KF  + SZ_QF;   // fp32 [B][Dv][S]
constexpr size_t OFF_Q3  = OFF_VT  + SZ_QF;
constexpr size_t OFF_K3  = OFF_Q3  + SZ_Q3;
constexpr size_t OFF_S   = OFF_K3  + SZ_Q3;
constexpr size_t OFF_S3  = OFF_S   + SZ_S;
constexpr size_t OFF_VT3 = OFF_S3  + SZ_S3;
constexpr size_t POOL_SZ = OFF_VT3 + SZ_VT3;

__device__ __align__(1024) static unsigned char g_pool[POOL_SZ];

// ---------------------------------------------------------------------------
// PTX helpers (sm_80-level features only — safe for plain sm_103 target)
// ---------------------------------------------------------------------------
static __device__ __forceinline__ uint32_t smem_u32(const void* p) {
    uint32_t a;
    asm("{ .reg .u64 t; cvta.to.shared.u64 t, %1; cvt.u32.u64 %0, t; }"
        : "=r"(a) : "l"(p));
    return a;
}
static __device__ __forceinline__ void cp16(uint32_t dst, const void* src) {
    asm volatile("cp.async.cg.shared.global [%0], [%1], 16;" :: "r"(dst), "l"(src));
}
static __device__ __forceinline__ void ldsm4(uint32_t& r0, uint32_t& r1,
                                             uint32_t& r2, uint32_t& r3, uint32_t addr) {
    asm volatile("ldmatrix.sync.aligned.m8n8.x4.shared.b16 {%0,%1,%2,%3}, [%4];"
                 : "=r"(r0), "=r"(r1), "=r"(r2), "=r"(r3) : "r"(addr));
}
static __device__ __forceinline__ void mma_bf16(float* d, const uint32_t* a,
                                                uint32_t b0, uint32_t b1) {
    asm volatile(
        "mma.sync.aligned.m16n8k16.row.col.f32.bf16.bf16.f32 "
        "{%0,%1,%2,%3}, {%4,%5,%6,%7}, {%8,%9}, {%0,%1,%2,%3};"
        : "+f"(d[0]), "+f"(d[1]), "+f"(d[2]), "+f"(d[3])
        : "r"(a[0]), "r"(a[1]), "r"(a[2]), "r"(a[3]), "r"(b0), "r"(b1));
}

// ---------------------------------------------------------------------------
// NT GEMM: C[M,N] = A[M,K3] @ B[N,K3]^T (+bias). bf16 in, fp32 out.
// CTA 128x128, 8 warps (warp tile 32x64), BK=64, 3-stage cp.async pipeline.
// TRANS: C stored as [b][n][s] with b = gm>>11, s = gm&2047 (for V^T).
// ---------------------------------------------------------------------------
#define STAGE_B 32768   // A 16KB + B 16KB per stage
#define SMEM_TOT (3 * STAGE_B)

template <bool TRANS, bool BIAS>
__global__ __launch_bounds__(256, 2)
void gemm_bf16(const __nv_bfloat16* __restrict__ A, const __nv_bfloat16* __restrict__ B,
               const float* __restrict__ bias, float* __restrict__ C,
               int N, int K3, long sA, long sB, long sC, int ldc)
{
    extern __shared__ char smem[];
    const uint32_t sb = smem_u32(smem);
    const int tid = threadIdx.x;
    const int lane = tid & 31;
    const int wid = tid >> 5;
    const int wm = wid & 3;        // 0..3 along M
    const int wn = wid >> 2;       // 0..1 along N

    const long z = blockIdx.z;
    A += z * sA; B += z * sB; C += z * sC;
    const int m0 = blockIdx.y * 128;
    const int n0 = blockIdx.x * 128;
    const int NC = K3 >> 6;        // chunks of 64

    auto prefetch = [&](int c) {
        const uint32_t st = sb + (c % 3) * STAGE_B;
        const __nv_bfloat16* Ab = A + (long)m0 * K3 + c * 64;
        const __nv_bfloat16* Bb = B + (long)n0 * K3 + c * 64;
#pragma unroll
        for (int i = 0; i < 4; i++) {
            int g = tid + i * 256;            // 0..1023
            int r = g >> 3, c8 = g & 7;
            uint32_t off = (uint32_t)(r * 128 + ((c8 ^ (r & 7)) << 4));
            cp16(st + off,         Ab + (long)r * K3 + c8 * 8);
            cp16(st + 16384 + off, Bb + (long)r * K3 + c8 * 8);
        }
    };

    // ldmatrix address components (per warp/lane)
    const int a_r  = wm * 32 + (lane & 15);
    const int a_c8 = lane >> 4;                          // +0/+1 k-group
    const uint32_t a_sw = (uint32_t)(a_r & 7);
    const int b_r  = wn * 64 + (lane & 7) + ((lane >> 4) << 3);
    const int b_c8 = (lane >> 3) & 1;
    const uint32_t b_sw = (uint32_t)(b_r & 7);

    float acc[2][8][4];
#pragma unroll
    for (int mi = 0; mi < 2; mi++)
#pragma unroll
        for (int nj = 0; nj < 8; nj++)
#pragma unroll
            for (int q = 0; q < 4; q++) acc[mi][nj][q] = 0.0f;

    prefetch(0);
    asm volatile("cp.async.commit_group;" ::: "memory");
    prefetch(1);
    asm volatile("cp.async.commit_group;" ::: "memory");

    for (int c = 0; c < NC; c++) {
        asm volatile("cp.async.wait_group 1;" ::: "memory");
        __syncthreads();
        if (c + 2 < NC) prefetch(c + 2);
        asm volatile("cp.async.commit_group;" ::: "memory");

        const uint32_t As = sb + (c % 3) * STAGE_B;
        const uint32_t Bs = As + 16384;
#pragma unroll
        for (int ks = 0; ks < 4; ks++) {
            uint32_t a[2][4];
#pragma unroll
            for (int mi = 0; mi < 2; mi++)
                ldsm4(a[mi][0], a[mi][1], a[mi][2], a[mi][3],
                      As + (uint32_t)((a_r + mi * 16) * 128)
                         + ((((uint32_t)(ks * 2 + a_c8)) ^ a_sw) << 4));
            uint32_t b[4][4];
#pragma unroll
            for (int pj = 0; pj < 4; pj++)
                ldsm4(b[pj][0], b[pj][1], b[pj][2], b[pj][3],
                      Bs + (uint32_t)((b_r + pj * 16) * 128)
                         + ((((uint32_t)(ks * 2 + b_c8)) ^ b_sw) << 4));
#pragma unroll
            for (int mi = 0; mi < 2; mi++)
#pragma unroll
                for (int nj = 0; nj < 8; nj++)
                    mma_bf16(acc[mi][nj], a[mi],
                             b[nj >> 1][(nj & 1) * 2], b[nj >> 1][(nj & 1) * 2 + 1]);
        }
        __syncthreads();
    }

    // ---- epilogue ----
    const int tg = lane >> 2;          // 0..7
    const int tq = (lane & 3) * 2;     // 0,2,4,6
#pragma unroll
    for (int mi = 0; mi < 2; mi++) {
        const int row0 = m0 + wm * 32 + mi * 16 + tg;
        const int row1 = row0 + 8;
#pragma unroll
        for (int nj = 0; nj < 8; nj++) {
            const int col = n0 + wn * 64 + nj * 8 + tq;
            float bx = 0.f, by = 0.f;
            if (BIAS) { bx = bias[col]; by = bias[col + 1]; }
            float v0 = acc[mi][nj][0] + bx, v1 = acc[mi][nj][1] + by;
            float v2 = acc[mi][nj][2] + bx, v3 = acc[mi][nj][3] + by;
            if (TRANS) {
                // C[b][col][s], b = row>>11, s = row&2047
                float* C0 = C + ((long)(row0 >> 11) * N + col) * 2048 + (row0 & 2047);
                float* C1 = C + ((long)(row1 >> 11) * N + col) * 2048 + (row1 & 2047);
                C0[0] = v0; C0[2048] = v1;
                C1[0] = v2; C1[2048] = v3;
            } else {
                float2* p0 = (float2*)(C + (long)row0 * ldc + col);
                float2* p1 = (float2*)(C + (long)row1 * ldc + col);
                *p0 = make_float2(v0, v1);
                *p1 = make_float2(v2, v3);
            }
        }
    }
}

// ---------------------------------------------------------------------------
// fp32 -> bf16 triple split: out[row, 3K] bf16; hi at [k], [offHi2+k]; lo [offLo+k]
// ---------------------------------------------------------------------------
static __device__ __forceinline__ uint32_t packbf(float x, float y) {
    __nv_bfloat162 h = __floats2bfloat162_rn(x, y);
    return *reinterpret_cast<uint32_t*>(&h);
}

__global__ __launch_bounds__(256)
void split3(const float* __restrict__ in, __nv_bfloat16* __restrict__ out,
            int kshift, long total4, int offHi2, int offLo)
{
    long i4 = (long)blockIdx.x * 256 + threadIdx.x;
    if (i4 >= total4) return;
    long e = i4 << 2;
    long row = e >> kshift;
    int k = (int)(e & ((1L << kshift) - 1));
    float4 v = ((const float4*)in)[i4];

    float hx = __bfloat162float(__float2bfloat16_rn(v.x));
    float hy = __bfloat162float(__float2bfloat16_rn(v.y));
    float hz = __bfloat162float(__float2bfloat16_rn(v.z));
    float hw = __bfloat162float(__float2bfloat16_rn(v.w));
    uint2 hp = make_uint2(packbf(hx, hy), packbf(hz, hw));
    uint2 lp = make_uint2(packbf(v.x - hx, v.y - hy), packbf(v.z - hz, v.w - hw));

    __nv_bfloat16* ob = out + row * 3 * (1L << kshift);
    *(uint2*)(ob + k)          = hp;
    *(uint2*)(ob + offHi2 + k) = hp;
    *(uint2*)(ob + offLo + k)  = lp;
}

// ---------------------------------------------------------------------------
// softmax over rows of [rows, 2048], then * scale (post-softmax, per reference)
// ---------------------------------------------------------------------------
static __inline__ __device__ float wrMax(float v) {
#pragma unroll
    for (int o = 16; o > 0; o >>= 1) v = fmaxf(v, __shfl_xor_sync(0xffffffffu, v, o));
    return v;
}
static __inline__ __device__ float wrSum(float v) {
#pragma unroll
    for (int o = 16; o > 0; o >>= 1) v += __shfl_xor_sync(0xffffffffu, v, o);
    return v;
}

__global__ __launch_bounds__(256)
void softmax_rows_2048(float* __restrict__ Sc, float scale)
{
    __shared__ float red[8];
    const long row = blockIdx.x;
    float* p = Sc + row * 2048;
    const int tid = threadIdx.x;
    const int lane = tid & 31;
    const int wid = tid >> 5;

    float v[8];
#pragma unroll
    for (int i = 0; i < 8; i++) v[i] = p[tid + i * 256];

    float m = -1e30f;
#pragma unroll
    for (int i = 0; i < 8; i++) m = fmaxf(m, v[i]);
    m = wrMax(m);
    if (lane == 0) red[wid] = m;
    __syncthreads();
    if (tid < 32) {
        float t = (lane < 8) ? red[lane] : -1e30f;
        t = wrMax(t);
        if (lane == 0) red[0] = t;
    }
    __syncthreads();
    m = red[0];
    __syncthreads();

    float s = 0.0f;
#pragma unroll
    for (int i = 0; i < 8; i++) { v[i] = __expf(v[i] - m); s += v[i]; }
    s = wrSum(s);
    if (lane == 0) red[wid] = s;
    __syncthreads();
    if (tid < 32) {
        float t = (lane < 8) ? red[lane] : 0.0f;
        t = wrSum(t);
        if (lane == 0) red[0] = t;
    }
    __syncthreads();
    s = red[0];

    float r = scale / s;
#pragma unroll
    for (int i = 0; i < 8; i++) p[tid + i * 256] = v[i] * r;
}

// ---------------------------------------------------------------------------
extern "C" void kernel_launch(void* const* d_in, const int* in_sizes, int n_in,
                              void* d_out, int out_size)
{
    const float* x  = (const float*)d_in[0];
    const float* Wq = (const float*)d_in[1];
    const float* bq = (const float*)d_in[2];
    const float* Wk = (const float*)d_in[3];
    const float* bk = (const float*)d_in[4];
    const float* Wv = (const float*)d_in[5];
    const float* bv = (const float*)d_in[6];
    float* out = (float*)d_out;

    unsigned char* pool;
    cudaGetSymbolAddress((void**)&pool, g_pool);
    __nv_bfloat16* x3  = (__nv_bfloat16*)(pool + OFF_X3);
    __nv_bfloat16* Wq3 = (__nv_bfloat16*)(pool + OFF_WQ3);
    __nv_bfloat16* Wk3 = (__nv_bfloat16*)(pool + OFF_WK3);
    __nv_bfloat16* Wv3 = (__nv_bfloat16*)(pool + OFF_WV3);
    float* Qf  = (float*)(pool + OFF_QF);
    float* Kf  = (float*)(pool + OFF_KF);
    float* Vt  = (float*)(pool + OFF_VT);
    __nv_bfloat16* Q3  = (__nv_bfloat16*)(pool + OFF_Q3);
    __nv_bfloat16* K3b = (__nv_bfloat16*)(pool + OFF_K3);
    float* Sm  = (float*)(pool + OFF_S);
    __nv_bfloat16* S3  = (__nv_bfloat16*)(pool + OFF_S3);
    __nv_bfloat16* Vt3 = (__nv_bfloat16*)(pool + OFF_VT3);

    cudaFuncSetAttribute(gemm_bf16<false, true>,
                         cudaFuncAttributeMaxDynamicSharedMemorySize, SMEM_TOT);
    cudaFuncSetAttribute(gemm_bf16<true, true>,
                         cudaFuncAttributeMaxDynamicSharedMemorySize, SMEM_TOT);
    cudaFuncSetAttribute(gemm_bf16<false, false>,
                         cudaFuncAttributeMaxDynamicSharedMemorySize, SMEM_TOT);

    dim3 blk(256);

    // ---- 1. split inputs: x (A-side), W* (B-side); K=1024, kshift=10 ----
    {
        long t4x = (long)BB * SS * DD / 4;
        split3<<<(unsigned)(t4x / 256), blk>>>(x, x3, 10, t4x, 2048, 1024);
        long t4w = (long)DD * DD / 4;
        split3<<<(unsigned)(t4w / 256), blk>>>(Wq, Wq3, 10, t4w, 1024, 2048);
        split3<<<(unsigned)(t4w / 256), blk>>>(Wk, Wk3, 10, t4w, 1024, 2048);
        split3<<<(unsigned)(t4w / 256), blk>>>(Wv, Wv3, 10, t4w, 1024, 2048);
    }

    // ---- 2. QKV projections: M=8192, N=1024, K3=3072 ----
    {
        dim3 g(DD / 128, (BB * SS) / 128, 1);
        gemm_bf16<false, true><<<g, blk, SMEM_TOT>>>(x3, Wq3, bq, Qf,
                                                     DD, 3 * DD, 0, 0, 0, DD);
        gemm_bf16<false, true><<<g, blk, SMEM_TOT>>>(x3, Wk3, bk, Kf,
                                                     DD, 3 * DD, 0, 0, 0, DD);
        gemm_bf16<true, true><<<g, blk, SMEM_TOT>>>(x3, Wv3, bv, Vt,
                                                    DD, 3 * DD, 0, 0, 0, DD);
    }

    // ---- 3. split Q (A-side), K (B-side): K=1024 ----
    {
        long t4 = (long)BB * SS * DD / 4;
        split3<<<(unsigned)(t4 / 256), blk>>>(Qf, Q3, 10, t4, 2048, 1024);
        split3<<<(unsigned)(t4 / 256), blk>>>(Kf, K3b, 10, t4, 1024, 2048);
    }

    // ---- 4. scores: per-batch M=N=2048, K3 = 3*DD = 3072  (R3 bug fixed) ----
    {
        dim3 g(SS / 128, SS / 128, BB);
        gemm_bf16<false, false><<<g, blk, SMEM_TOT>>>(Q3, K3b, nullptr, Sm,
                                                      SS, 3 * DD,
                                                      (long)SS * 3 * DD, (long)SS * 3 * DD,
                                                      (long)SS * SS, SS);
    }

    // ---- 5. softmax (post-softmax scale 1/sqrt(1024)) ----
    softmax_rows_2048<<<BB * SS, blk>>>(Sm, 0.03125f);

    // ---- 6. split probs (A-side) and Vt (B-side): K=2048, kshift=11 ----
    {
        long t4s = (long)BB * SS * SS / 4;
        split3<<<(unsigned)(t4s / 256), blk>>>(Sm, S3, 11, t4s, 4096, 2048);
        long t4v = (long)BB * DD * SS / 4;
        split3<<<(unsigned)(t4v / 256), blk>>>(Vt, Vt3, 11, t4v, 2048, 4096);
    }

    // ---- 7. out: per-batch M=2048, N=1024, K3 = 3*SS = 6144 ----
    {
        dim3 g(DD / 128, SS / 128, BB);
        gemm_bf16<false, false><<<g, blk, SMEM_TOT>>>(S3, Vt3, nullptr, out,
                                                      DD, 3 * SS,
                                                      (long)SS * 3 * SS, (long)DD * 3 * SS,
                                                      (long)SS * DD, DD);
    }
}

// round 6
// speedup vs baseline: 2.7387x; 1.0101x over previous
#include <cuda_runtime.h>
#include <cuda_bf16.h>
#include <cstdint>

// ============================================================================
// Self_Attention on GB300 (sm_103a), Round 6 (= R5 resubmit after infra fail):
// bf16x3 mma.sync GEMMs with fused split epilogues (Q/K/V projections and
// softmax emit split bf16 operand layouts directly).
//   Q = x Wq^T + bq ; K = x Wk^T + bk ; V = x Wv^T + bv
//   out = (softmax(Q K^T) / sqrt(Dk)) @ V
// Error-compensated bf16: A' = [Ah|Al|Ah], B' = [Bh|Bh|Bl], K' = 3K
// ============================================================================

#define BB 4
#define SS 2048
#define DD 1024

// ---------------------------------------------------------------------------
// Scratch pool
// ---------------------------------------------------------------------------
constexpr size_t SZ_X3  = (size_t)BB * SS * 3 * DD * 2;     // 48 MB bf16
constexpr size_t SZ_W3  = (size_t)DD * 3 * DD * 2;          // 6 MB bf16
constexpr size_t SZ_Q3  = (size_t)BB * SS * 3 * DD * 2;     // 48 MB bf16
constexpr size_t SZ_S   = (size_t)BB * SS * SS * 4;         // 64 MB fp32
constexpr size_t SZ_S3  = (size_t)BB * SS * 3 * SS * 2;     // 96 MB bf16
constexpr size_t SZ_VT3 = (size_t)BB * DD * 3 * SS * 2;     // 48 MB bf16

constexpr size_t OFF_X3  = 0;
constexpr size_t OFF_WQ3 = OFF_X3  + SZ_X3;
constexpr size_t OFF_WK3 = OFF_WQ3 + SZ_W3;
constexpr size_t OFF_WV3 = OFF_WK3 + SZ_W3;
constexpr size_t OFF_Q3  = OFF_WV3 + SZ_W3;
constexpr size_t OFF_K3  = OFF_Q3  + SZ_Q3;
constexpr size_t OFF_S   = OFF_K3  + SZ_Q3;
constexpr size_t OFF_S3  = OFF_S   + SZ_S;
constexpr size_t OFF_VT3 = OFF_S3  + SZ_S3;
constexpr size_t POOL_SZ = OFF_VT3 + SZ_VT3;

__device__ __align__(1024) static unsigned char g_pool[POOL_SZ];

// ---------------------------------------------------------------------------
// PTX helpers (sm_80-level only — plain sm_103 target safe)
// ---------------------------------------------------------------------------
static __device__ __forceinline__ uint32_t smem_u32(const void* p) {
    uint32_t a;
    asm("{ .reg .u64 t; cvta.to.shared.u64 t, %1; cvt.u32.u64 %0, t; }"
        : "=r"(a) : "l"(p));
    return a;
}
static __device__ __forceinline__ void cp16(uint32_t dst, const void* src) {
    asm volatile("cp.async.cg.shared.global [%0], [%1], 16;" :: "r"(dst), "l"(src));
}
static __device__ __forceinline__ void ldsm4(uint32_t& r0, uint32_t& r1,
                                             uint32_t& r2, uint32_t& r3, uint32_t addr) {
    asm volatile("ldmatrix.sync.aligned.m8n8.x4.shared.b16 {%0,%1,%2,%3}, [%4];"
                 : "=r"(r0), "=r"(r1), "=r"(r2), "=r"(r3) : "r"(addr));
}
static __device__ __forceinline__ void mma_bf16(float* d, const uint32_t* a,
                                                uint32_t b0, uint32_t b1) {
    asm volatile(
        "mma.sync.aligned.m16n8k16.row.col.f32.bf16.bf16.f32 "
        "{%0,%1,%2,%3}, {%4,%5,%6,%7}, {%8,%9}, {%0,%1,%2,%3};"
        : "+f"(d[0]), "+f"(d[1]), "+f"(d[2]), "+f"(d[3])
        : "r"(a[0]), "r"(a[1]), "r"(a[2]), "r"(a[3]), "r"(b0), "r"(b1));
}
static __device__ __forceinline__ uint32_t packbf(float x, float y) {
    __nv_bfloat162 h = __floats2bfloat162_rn(x, y);
    return *reinterpret_cast<uint32_t*>(&h);
}
// split a pair and write hi (twice) + lo into a bf16 row at given offsets
static __device__ __forceinline__ void wsplit2(__nv_bfloat16* base, int offHi2,
                                               int offLo, float x, float y) {
    float hx = __bfloat162float(__float2bfloat16_rn(x));
    float hy = __bfloat162float(__float2bfloat16_rn(y));
    uint32_t hp = packbf(hx, hy);
    uint32_t lp = packbf(x - hx, y - hy);
    *(uint32_t*)(base)          = hp;
    *(uint32_t*)(base + offHi2) = hp;
    *(uint32_t*)(base + offLo)  = lp;
}

// ---------------------------------------------------------------------------
// NT GEMM: C = A[M,K3] @ B[N,K3]^T (+bias). bf16 in.
// CTA 128x128, 8 warps (warp tile 32x64), BK=64, 3-stage cp.async pipeline.
// MODE 0: C fp32 row-major (ldc)
// MODE 1: C bf16 split rows: C3 + row*ldc + {col, col+offHi2 (hi), col+offLo (lo)}
// MODE 2: C bf16 split transposed for Vt3: base = C3 + ((row>>11)*1024+col)*6144
//         + (row&2047); base[0]=hi, base[2048]=hi, base[4096]=lo
// ---------------------------------------------------------------------------
#define STAGE_B 32768
#define SMEM_TOT (3 * STAGE_B)

template <int MODE, bool BIAS>
__global__ __launch_bounds__(256, 2)
void gemm_bf16(const __nv_bfloat16* __restrict__ A, const __nv_bfloat16* __restrict__ B,
               const float* __restrict__ bias, void* __restrict__ Cv,
               int K3, long sA, long sB, long sC, int ldc, int offHi2, int offLo)
{
    extern __shared__ char smem[];
    const uint32_t sb = smem_u32(smem);
    const int tid = threadIdx.x;
    const int lane = tid & 31;
    const int wid = tid >> 5;
    const int wm = wid & 3;
    const int wn = wid >> 2;

    const long z = blockIdx.z;
    A += z * sA; B += z * sB;
    const int m0 = blockIdx.y * 128;
    const int n0 = blockIdx.x * 128;
    const int NC = K3 >> 6;

    auto prefetch = [&](int c) {
        const uint32_t st = sb + (c % 3) * STAGE_B;
        const __nv_bfloat16* Ab = A + (long)m0 * K3 + c * 64;
        const __nv_bfloat16* Bb = B + (long)n0 * K3 + c * 64;
#pragma unroll
        for (int i = 0; i < 4; i++) {
            int g = tid + i * 256;
            int r = g >> 3, c8 = g & 7;
            uint32_t off = (uint32_t)(r * 128 + ((c8 ^ (r & 7)) << 4));
            cp16(st + off,         Ab + (long)r * K3 + c8 * 8);
            cp16(st + 16384 + off, Bb + (long)r * K3 + c8 * 8);
        }
    };

    const int a_r  = wm * 32 + (lane & 15);
    const int a_c8 = lane >> 4;
    const uint32_t a_sw = (uint32_t)(a_r & 7);
    const int b_r  = wn * 64 + (lane & 7) + ((lane >> 4) << 3);
    const int b_c8 = (lane >> 3) & 1;
    const uint32_t b_sw = (uint32_t)(b_r & 7);

    float acc[2][8][4];
#pragma unroll
    for (int mi = 0; mi < 2; mi++)
#pragma unroll
        for (int nj = 0; nj < 8; nj++)
#pragma unroll
            for (int q = 0; q < 4; q++) acc[mi][nj][q] = 0.0f;

    prefetch(0);
    asm volatile("cp.async.commit_group;" ::: "memory");
    prefetch(1);
    asm volatile("cp.async.commit_group;" ::: "memory");

    for (int c = 0; c < NC; c++) {
        asm volatile("cp.async.wait_group 1;" ::: "memory");
        __syncthreads();
        if (c + 2 < NC) prefetch(c + 2);
        asm volatile("cp.async.commit_group;" ::: "memory");

        const uint32_t As = sb + (c % 3) * STAGE_B;
        const uint32_t Bs = As + 16384;
#pragma unroll
        for (int ks = 0; ks < 4; ks++) {
            uint32_t a[2][4];
#pragma unroll
            for (int mi = 0; mi < 2; mi++)
                ldsm4(a[mi][0], a[mi][1], a[mi][2], a[mi][3],
                      As + (uint32_t)((a_r + mi * 16) * 128)
                         + ((((uint32_t)(ks * 2 + a_c8)) ^ a_sw) << 4));
            uint32_t b[4][4];
#pragma unroll
            for (int pj = 0; pj < 4; pj++)
                ldsm4(b[pj][0], b[pj][1], b[pj][2], b[pj][3],
                      Bs + (uint32_t)((b_r + pj * 16) * 128)
                         + ((((uint32_t)(ks * 2 + b_c8)) ^ b_sw) << 4));
#pragma unroll
            for (int mi = 0; mi < 2; mi++)
#pragma unroll
                for (int nj = 0; nj < 8; nj++)
                    mma_bf16(acc[mi][nj], a[mi],
                             b[nj >> 1][(nj & 1) * 2], b[nj >> 1][(nj & 1) * 2 + 1]);
        }
        __syncthreads();
    }

    // ---- epilogue ----
    const int tg = lane >> 2;
    const int tq = (lane & 3) * 2;
#pragma unroll
    for (int mi = 0; mi < 2; mi++) {
        const int row0 = m0 + wm * 32 + mi * 16 + tg;
        const int row1 = row0 + 8;
#pragma unroll
        for (int nj = 0; nj < 8; nj++) {
            const int col = n0 + wn * 64 + nj * 8 + tq;
            float bx = 0.f, by = 0.f;
            if (BIAS) { bx = bias[col]; by = bias[col + 1]; }
            float v0 = acc[mi][nj][0] + bx, v1 = acc[mi][nj][1] + by;
            float v2 = acc[mi][nj][2] + bx, v3 = acc[mi][nj][3] + by;
            if (MODE == 0) {
                float* C = (float*)Cv + z * sC;
                *(float2*)(C + (long)row0 * ldc + col) = make_float2(v0, v1);
                *(float2*)(C + (long)row1 * ldc + col) = make_float2(v2, v3);
            } else if (MODE == 1) {
                __nv_bfloat16* C3 = (__nv_bfloat16*)Cv;
                wsplit2(C3 + (long)row0 * ldc + col, offHi2, offLo, v0, v1);
                wsplit2(C3 + (long)row1 * ldc + col, offHi2, offLo, v2, v3);
            } else {
                // MODE 2: Vt3[b][v][3*2048] = [Vh | Vh | Vl] along s
                __nv_bfloat16* C3 = (__nv_bfloat16*)Cv;
                const float vv[4] = {v0, v1, v2, v3};
                const int rr[2] = {row0, row1};
#pragma unroll
                for (int h = 0; h < 2; h++) {
                    const int row = rr[h];
                    __nv_bfloat16* b0 =
                        C3 + ((long)(row >> 11) * 1024 + col) * 6144 + (row & 2047);
#pragma unroll
                    for (int e = 0; e < 2; e++) {
                        float x = vv[h * 2 + e];
                        float hx = __bfloat162float(__float2bfloat16_rn(x));
                        __nv_bfloat16* bp = b0 + (long)e * 6144;
                        __nv_bfloat16 hb = __float2bfloat16_rn(hx);
                        bp[0]    = hb;
                        bp[2048] = hb;
                        bp[4096] = __float2bfloat16_rn(x - hx);
                    }
                }
            }
        }
    }
}

// ---------------------------------------------------------------------------
// fp32 -> bf16 triple split (only for raw inputs x / W now)
// ---------------------------------------------------------------------------
__global__ __launch_bounds__(256)
void split3(const float* __restrict__ in, __nv_bfloat16* __restrict__ out,
            int kshift, long total4, int offHi2, int offLo)
{
    long i4 = (long)blockIdx.x * 256 + threadIdx.x;
    if (i4 >= total4) return;
    long e = i4 << 2;
    long row = e >> kshift;
    int k = (int)(e & ((1L << kshift) - 1));
    float4 v = ((const float4*)in)[i4];

    float hx = __bfloat162float(__float2bfloat16_rn(v.x));
    float hy = __bfloat162float(__float2bfloat16_rn(v.y));
    float hz = __bfloat162float(__float2bfloat16_rn(v.z));
    float hw = __bfloat162float(__float2bfloat16_rn(v.w));
    uint2 hp = make_uint2(packbf(hx, hy), packbf(hz, hw));
    uint2 lp = make_uint2(packbf(v.x - hx, v.y - hy), packbf(v.z - hz, v.w - hw));

    __nv_bfloat16* ob = out + row * 3 * (1L << kshift);
    *(uint2*)(ob + k)          = hp;
    *(uint2*)(ob + offHi2 + k) = hp;
    *(uint2*)(ob + offLo + k)  = lp;
}

// ---------------------------------------------------------------------------
// softmax over rows of Sm [rows, 2048], * scale, fused triple-split to S3:
//   S3[row][s] = hi, S3[row][2048+s] = lo, S3[row][4096+s] = hi  ([Ah|Al|Ah])
// ---------------------------------------------------------------------------
static __inline__ __device__ float wrMax(float v) {
#pragma unroll
    for (int o = 16; o > 0; o >>= 1) v = fmaxf(v, __shfl_xor_sync(0xffffffffu, v, o));
    return v;
}
static __inline__ __device__ float wrSum(float v) {
#pragma unroll
    for (int o = 16; o > 0; o >>= 1) v += __shfl_xor_sync(0xffffffffu, v, o);
    return v;
}

__global__ __launch_bounds__(256)
void softmax_split(const float* __restrict__ Sm, __nv_bfloat16* __restrict__ S3,
                   float scale)
{
    __shared__ float red[8];
    const long row = blockIdx.x;
    const float* p = Sm + row * 2048;
    const int tid = threadIdx.x;
    const int lane = tid & 31;
    const int wid = tid >> 5;

    float v[8];
#pragma unroll
    for (int i = 0; i < 8; i++) v[i] = p[tid + i * 256];

    float m = -1e30f;
#pragma unroll
    for (int i = 0; i < 8; i++) m = fmaxf(m, v[i]);
    m = wrMax(m);
    if (lane == 0) red[wid] = m;
    __syncthreads();
    if (tid < 32) {
        float t = (lane < 8) ? red[lane] : -1e30f;
        t = wrMax(t);
        if (lane == 0) red[0] = t;
    }
    __syncthreads();
    m = red[0];
    __syncthreads();

    float s = 0.0f;
#pragma unroll
    for (int i = 0; i < 8; i++) { v[i] = __expf(v[i] - m); s += v[i]; }
    s = wrSum(s);
    if (lane == 0) red[wid] = s;
    __syncthreads();
    if (tid < 32) {
        float t = (lane < 8) ? red[lane] : 0.0f;
        t = wrSum(t);
        if (lane == 0) red[0] = t;
    }
    __syncthreads();
    s = red[0];

    float r = scale / s;
    __nv_bfloat16* ob = S3 + row * 6144;
#pragma unroll
    for (int i = 0; i < 8; i++) {
        int idx = tid + i * 256;
        float x = v[i] * r;
        float hx = __bfloat162float(__float2bfloat16_rn(x));
        __nv_bfloat16 hb = __float2bfloat16_rn(hx);
        ob[idx]        = hb;
        ob[4096 + idx] = hb;
        ob[2048 + idx] = __float2bfloat16_rn(x - hx);
    }
}

// ---------------------------------------------------------------------------
extern "C" void kernel_launch(void* const* d_in, const int* in_sizes, int n_in,
                              void* d_out, int out_size)
{
    const float* x  = (const float*)d_in[0];
    const float* Wq = (const float*)d_in[1];
    const float* bq = (const float*)d_in[2];
    const float* Wk = (const float*)d_in[3];
    const float* bk = (const float*)d_in[4];
    const float* Wv = (const float*)d_in[5];
    const float* bv = (const float*)d_in[6];
    float* out = (float*)d_out;

    unsigned char* pool;
    cudaGetSymbolAddress((void**)&pool, g_pool);
    __nv_bfloat16* x3  = (__nv_bfloat16*)(pool + OFF_X3);
    __nv_bfloat16* Wq3 = (__nv_bfloat16*)(pool + OFF_WQ3);
    __nv_bfloat16* Wk3 = (__nv_bfloat16*)(pool + OFF_WK3);
    __nv_bfloat16* Wv3 = (__nv_bfloat16*)(pool + OFF_WV3);
    __nv_bfloat16* Q3  = (__nv_bfloat16*)(pool + OFF_Q3);
    __nv_bfloat16* K3b = (__nv_bfloat16*)(pool + OFF_K3);
    float*         Sm  = (float*)(pool + OFF_S);
    __nv_bfloat16* S3  = (__nv_bfloat16*)(pool + OFF_S3);
    __nv_bfloat16* Vt3 = (__nv_bfloat16*)(pool + OFF_VT3);

    cudaFuncSetAttribute(gemm_bf16<0, false>,
                         cudaFuncAttributeMaxDynamicSharedMemorySize, SMEM_TOT);
    cudaFuncSetAttribute(gemm_bf16<1, true>,
                         cudaFuncAttributeMaxDynamicSharedMemorySize, SMEM_TOT);
    cudaFuncSetAttribute(gemm_bf16<2, true>,
                         cudaFuncAttributeMaxDynamicSharedMemorySize, SMEM_TOT);

    dim3 blk(256);

    // ---- 1. split raw inputs: x (A-side: hi@0, lo@+1024, hi@+2048),
    //         W* (B-side: hi@0, hi@+1024, lo@+2048); K=1024 ----
    {
        long t4x = (long)BB * SS * DD / 4;
        split3<<<(unsigned)(t4x / 256), blk>>>(x, x3, 10, t4x, 2048, 1024);
        long t4w = (long)DD * DD / 4;
        split3<<<(unsigned)(t4w / 256), blk>>>(Wq, Wq3, 10, t4w, 1024, 2048);
        split3<<<(unsigned)(t4w / 256), blk>>>(Wk, Wk3, 10, t4w, 1024, 2048);
        split3<<<(unsigned)(t4w / 256), blk>>>(Wv, Wv3, 10, t4w, 1024, 2048);
    }

    // ---- 2. QKV projections (M=8192, N=1024, K3=3072) with fused splits ----
    {
        dim3 g(DD / 128, (BB * SS) / 128, 1);
        // Q -> A-side split rows (ldc=3072, hi@+2048, lo@+1024)
        gemm_bf16<1, true><<<g, blk, SMEM_TOT>>>(x3, Wq3, bq, Q3,
                                                 3 * DD, 0, 0, 0, 3 * DD, 2048, 1024);
        // K -> B-side split rows (hi@+1024, lo@+2048)
        gemm_bf16<1, true><<<g, blk, SMEM_TOT>>>(x3, Wk3, bk, K3b,
                                                 3 * DD, 0, 0, 0, 3 * DD, 1024, 2048);
        // V -> transposed B-side split (Vt3[b][v][3*2048])
        gemm_bf16<2, true><<<g, blk, SMEM_TOT>>>(x3, Wv3, bv, Vt3,
                                                 3 * DD, 0, 0, 0, 0, 0, 0);
    }

    // ---- 3. scores: per-batch M=N=2048, K3=3072 -> Sm fp32 ----
    {
        dim3 g(SS / 128, SS / 128, BB);
        gemm_bf16<0, false><<<g, blk, SMEM_TOT>>>(Q3, K3b, nullptr, Sm,
                                                  3 * DD,
                                                  (long)SS * 3 * DD, (long)SS * 3 * DD,
                                                  (long)SS * SS, SS, 0, 0);
    }

    // ---- 4. softmax + fused probs split (post-softmax scale 1/32) ----
    softmax_split<<<BB * SS, blk>>>(Sm, S3, 0.03125f);

    // ---- 5. out: per-batch M=2048, N=1024, K3=6144 ----
    {
        dim3 g(DD / 128, SS / 128, BB);
        gemm_bf16<0, false><<<g, blk, SMEM_TOT>>>(S3, Vt3, nullptr, out,
                                                  3 * SS,
                                                  (long)SS * 3 * SS, (long)DD * 3 * SS,
                                                  (long)SS * DD, DD, 0, 0);
    }
}

// round 7
// speedup vs baseline: 2.8613x; 1.0448x over previous
#include <cuda_runtime.h>
#include <cuda_bf16.h>
#include <cstdint>

// ============================================================================
// Self_Attention on GB300 (sm_103a), Round 7: bf16x3 mma.sync GEMMs,
// warp tile enlarged 32x64 -> 64x64 (CTA 128x128, 4 warps / 128 threads)
// to double HMMA density per issue slot. Fused split epilogues kept.
//   Q = x Wq^T + bq ; K = x Wk^T + bk ; V = x Wv^T + bv
//   out = (softmax(Q K^T) / sqrt(Dk)) @ V
// Error-compensated bf16: A' = [Ah|Al|Ah], B' = [Bh|Bh|Bl], K' = 3K
// ============================================================================

#define BB 4
#define SS 2048
#define DD 1024

// ---------------------------------------------------------------------------
// Scratch pool
// ---------------------------------------------------------------------------
constexpr size_t SZ_X3  = (size_t)BB * SS * 3 * DD * 2;
constexpr size_t SZ_W3  = (size_t)DD * 3 * DD * 2;
constexpr size_t SZ_Q3  = (size_t)BB * SS * 3 * DD * 2;
constexpr size_t SZ_S   = (size_t)BB * SS * SS * 4;
constexpr size_t SZ_S3  = (size_t)BB * SS * 3 * SS * 2;
constexpr size_t SZ_VT3 = (size_t)BB * DD * 3 * SS * 2;

constexpr size_t OFF_X3  = 0;
constexpr size_t OFF_WQ3 = OFF_X3  + SZ_X3;
constexpr size_t OFF_WK3 = OFF_WQ3 + SZ_W3;
constexpr size_t OFF_WV3 = OFF_WK3 + SZ_W3;
constexpr size_t OFF_Q3  = OFF_WV3 + SZ_W3;
constexpr size_t OFF_K3  = OFF_Q3  + SZ_Q3;
constexpr size_t OFF_S   = OFF_K3  + SZ_Q3;
constexpr size_t OFF_S3  = OFF_S   + SZ_S;
constexpr size_t OFF_VT3 = OFF_S3  + SZ_S3;
constexpr size_t POOL_SZ = OFF_VT3 + SZ_VT3;

__device__ __align__(1024) static unsigned char g_pool[POOL_SZ];

// ---------------------------------------------------------------------------
// PTX helpers
// ---------------------------------------------------------------------------
static __device__ __forceinline__ uint32_t smem_u32(const void* p) {
    uint32_t a;
    asm("{ .reg .u64 t; cvta.to.shared.u64 t, %1; cvt.u32.u64 %0, t; }"
        : "=r"(a) : "l"(p));
    return a;
}
static __device__ __forceinline__ void cp16(uint32_t dst, const void* src) {
    asm volatile("cp.async.cg.shared.global [%0], [%1], 16;" :: "r"(dst), "l"(src));
}
static __device__ __forceinline__ void ldsm4(uint32_t& r0, uint32_t& r1,
                                             uint32_t& r2, uint32_t& r3, uint32_t addr) {
    asm volatile("ldmatrix.sync.aligned.m8n8.x4.shared.b16 {%0,%1,%2,%3}, [%4];"
                 : "=r"(r0), "=r"(r1), "=r"(r2), "=r"(r3) : "r"(addr));
}
static __device__ __forceinline__ void mma_bf16(float* d, const uint32_t* a,
                                                uint32_t b0, uint32_t b1) {
    asm volatile(
        "mma.sync.aligned.m16n8k16.row.col.f32.bf16.bf16.f32 "
        "{%0,%1,%2,%3}, {%4,%5,%6,%7}, {%8,%9}, {%0,%1,%2,%3};"
        : "+f"(d[0]), "+f"(d[1]), "+f"(d[2]), "+f"(d[3])
        : "r"(a[0]), "r"(a[1]), "r"(a[2]), "r"(a[3]), "r"(b0), "r"(b1));
}
static __device__ __forceinline__ uint32_t packbf(float x, float y) {
    __nv_bfloat162 h = __floats2bfloat162_rn(x, y);
    return *reinterpret_cast<uint32_t*>(&h);
}
static __device__ __forceinline__ void wsplit2(__nv_bfloat16* base, int offHi2,
                                               int offLo, float x, float y) {
    float hx = __bfloat162float(__float2bfloat16_rn(x));
    float hy = __bfloat162float(__float2bfloat16_rn(y));
    uint32_t hp = packbf(hx, hy);
    uint32_t lp = packbf(x - hx, y - hy);
    *(uint32_t*)(base)          = hp;
    *(uint32_t*)(base + offHi2) = hp;
    *(uint32_t*)(base + offLo)  = lp;
}

// ---------------------------------------------------------------------------
// NT GEMM: C = A[M,K3] @ B[N,K3]^T (+bias). bf16 in.
// CTA 128x128, 4 warps (warp tile 64x64), BK=64, 3-stage cp.async pipeline.
// MODE 0: C fp32 row-major (ldc)
// MODE 1: C bf16 split rows (hi, hi@offHi2, lo@offLo)
// MODE 2: C bf16 split transposed for Vt3[b][v][3*2048]
// ---------------------------------------------------------------------------
#define STAGE_B 32768
#define SMEM_TOT (3 * STAGE_B)

template <int MODE, bool BIAS>
__global__ __launch_bounds__(128, 2)
void gemm_bf16(const __nv_bfloat16* __restrict__ A, const __nv_bfloat16* __restrict__ B,
               const float* __restrict__ bias, void* __restrict__ Cv,
               int K3, long sA, long sB, long sC, int ldc, int offHi2, int offLo)
{
    extern __shared__ char smem[];
    const uint32_t sb = smem_u32(smem);
    const int tid = threadIdx.x;
    const int lane = tid & 31;
    const int wid = tid >> 5;      // 0..3
    const int wm = wid & 1;        // 2 warps along M
    const int wn = wid >> 1;       // 2 warps along N

    const long z = blockIdx.z;
    A += z * sA; B += z * sB;
    const int m0 = blockIdx.y * 128;
    const int n0 = blockIdx.x * 128;
    const int NC = K3 >> 6;

    auto prefetch = [&](int c) {
        const uint32_t st = sb + (c % 3) * STAGE_B;
        const __nv_bfloat16* Ab = A + (long)m0 * K3 + c * 64;
        const __nv_bfloat16* Bb = B + (long)n0 * K3 + c * 64;
#pragma unroll
        for (int i = 0; i < 8; i++) {
            int g = tid + i * 128;            // 0..1023
            int r = g >> 3, c8 = g & 7;
            uint32_t off = (uint32_t)(r * 128 + ((c8 ^ (r & 7)) << 4));
            cp16(st + off,         Ab + (long)r * K3 + c8 * 8);
            cp16(st + 16384 + off, Bb + (long)r * K3 + c8 * 8);
        }
    };

    const int a_r  = wm * 64 + (lane & 15);
    const int a_c8 = lane >> 4;
    const uint32_t a_sw = (uint32_t)(a_r & 7);
    const int b_r  = wn * 64 + (lane & 7) + ((lane >> 4) << 3);
    const int b_c8 = (lane >> 3) & 1;
    const uint32_t b_sw = (uint32_t)(b_r & 7);

    float acc[4][8][4];
#pragma unroll
    for (int mi = 0; mi < 4; mi++)
#pragma unroll
        for (int nj = 0; nj < 8; nj++)
#pragma unroll
            for (int q = 0; q < 4; q++) acc[mi][nj][q] = 0.0f;

    prefetch(0);
    asm volatile("cp.async.commit_group;" ::: "memory");
    prefetch(1);
    asm volatile("cp.async.commit_group;" ::: "memory");

    for (int c = 0; c < NC; c++) {
        asm volatile("cp.async.wait_group 1;" ::: "memory");
        __syncthreads();
        if (c + 2 < NC) prefetch(c + 2);
        asm volatile("cp.async.commit_group;" ::: "memory");

        const uint32_t As = sb + (c % 3) * STAGE_B;
        const uint32_t Bs = As + 16384;
#pragma unroll
        for (int ks = 0; ks < 4; ks++) {
            uint32_t a[4][4];
#pragma unroll
            for (int mi = 0; mi < 4; mi++)
                ldsm4(a[mi][0], a[mi][1], a[mi][2], a[mi][3],
                      As + (uint32_t)((a_r + mi * 16) * 128)
                         + ((((uint32_t)(ks * 2 + a_c8)) ^ a_sw) << 4));
            uint32_t b[4][4];
#pragma unroll
            for (int pj = 0; pj < 4; pj++)
                ldsm4(b[pj][0], b[pj][1], b[pj][2], b[pj][3],
                      Bs + (uint32_t)((b_r + pj * 16) * 128)
                         + ((((uint32_t)(ks * 2 + b_c8)) ^ b_sw) << 4));
#pragma unroll
            for (int mi = 0; mi < 4; mi++)
#pragma unroll
                for (int nj = 0; nj < 8; nj++)
                    mma_bf16(acc[mi][nj], a[mi],
                             b[nj >> 1][(nj & 1) * 2], b[nj >> 1][(nj & 1) * 2 + 1]);
        }
        __syncthreads();
    }

    // ---- epilogue ----
    const int tg = lane >> 2;
    const int tq = (lane & 3) * 2;
#pragma unroll
    for (int mi = 0; mi < 4; mi++) {
        const int row0 = m0 + wm * 64 + mi * 16 + tg;
        const int row1 = row0 + 8;
#pragma unroll
        for (int nj = 0; nj < 8; nj++) {
            const int col = n0 + wn * 64 + nj * 8 + tq;
            float bx = 0.f, by = 0.f;
            if (BIAS) { bx = bias[col]; by = bias[col + 1]; }
            float v0 = acc[mi][nj][0] + bx, v1 = acc[mi][nj][1] + by;
            float v2 = acc[mi][nj][2] + bx, v3 = acc[mi][nj][3] + by;
            if (MODE == 0) {
                float* C = (float*)Cv + z * sC;
                *(float2*)(C + (long)row0 * ldc + col) = make_float2(v0, v1);
                *(float2*)(C + (long)row1 * ldc + col) = make_float2(v2, v3);
            } else if (MODE == 1) {
                __nv_bfloat16* C3 = (__nv_bfloat16*)Cv;
                wsplit2(C3 + (long)row0 * ldc + col, offHi2, offLo, v0, v1);
                wsplit2(C3 + (long)row1 * ldc + col, offHi2, offLo, v2, v3);
            } else {
                __nv_bfloat16* C3 = (__nv_bfloat16*)Cv;
                const float vv[4] = {v0, v1, v2, v3};
                const int rr[2] = {row0, row1};
#pragma unroll
                for (int h = 0; h < 2; h++) {
                    const int row = rr[h];
                    __nv_bfloat16* b0 =
                        C3 + ((long)(row >> 11) * 1024 + col) * 6144 + (row & 2047);
#pragma unroll
                    for (int e = 0; e < 2; e++) {
                        float x = vv[h * 2 + e];
                        float hx = __bfloat162float(__float2bfloat16_rn(x));
                        __nv_bfloat16* bp = b0 + (long)e * 6144;
                        __nv_bfloat16 hb = __float2bfloat16_rn(hx);
                        bp[0]    = hb;
                        bp[2048] = hb;
                        bp[4096] = __float2bfloat16_rn(x - hx);
                    }
                }
            }
        }
    }
}

// ---------------------------------------------------------------------------
// fp32 -> bf16 triple split (raw inputs x / W only)
// ---------------------------------------------------------------------------
__global__ __launch_bounds__(256)
void split3(const float* __restrict__ in, __nv_bfloat16* __restrict__ out,
            int kshift, long total4, int offHi2, int offLo)
{
    long i4 = (long)blockIdx.x * 256 + threadIdx.x;
    if (i4 >= total4) return;
    long e = i4 << 2;
    long row = e >> kshift;
    int k = (int)(e & ((1L << kshift) - 1));
    float4 v = ((const float4*)in)[i4];

    float hx = __bfloat162float(__float2bfloat16_rn(v.x));
    float hy = __bfloat162float(__float2bfloat16_rn(v.y));
    float hz = __bfloat162float(__float2bfloat16_rn(v.z));
    float hw = __bfloat162float(__float2bfloat16_rn(v.w));
    uint2 hp = make_uint2(packbf(hx, hy), packbf(hz, hw));
    uint2 lp = make_uint2(packbf(v.x - hx, v.y - hy), packbf(v.z - hz, v.w - hw));

    __nv_bfloat16* ob = out + row * 3 * (1L << kshift);
    *(uint2*)(ob + k)          = hp;
    *(uint2*)(ob + offHi2 + k) = hp;
    *(uint2*)(ob + offLo + k)  = lp;
}

// ---------------------------------------------------------------------------
// softmax + fused probs split
// ---------------------------------------------------------------------------
static __inline__ __device__ float wrMax(float v) {
#pragma unroll
    for (int o = 16; o > 0; o >>= 1) v = fmaxf(v, __shfl_xor_sync(0xffffffffu, v, o));
    return v;
}
static __inline__ __device__ float wrSum(float v) {
#pragma unroll
    for (int o = 16; o > 0; o >>= 1) v += __shfl_xor_sync(0xffffffffu, v, o);
    return v;
}

__global__ __launch_bounds__(256)
void softmax_split(const float* __restrict__ Sm, __nv_bfloat16* __restrict__ S3,
                   float scale)
{
    __shared__ float red[8];
    const long row = blockIdx.x;
    const float* p = Sm + row * 2048;
    const int tid = threadIdx.x;
    const int lane = tid & 31;
    const int wid = tid >> 5;

    float v[8];
#pragma unroll
    for (int i = 0; i < 8; i++) v[i] = p[tid + i * 256];

    float m = -1e30f;
#pragma unroll
    for (int i = 0; i < 8; i++) m = fmaxf(m, v[i]);
    m = wrMax(m);
    if (lane == 0) red[wid] = m;
    __syncthreads();
    if (tid < 32) {
        float t = (lane < 8) ? red[lane] : -1e30f;
        t = wrMax(t);
        if (lane == 0) red[0] = t;
    }
    __syncthreads();
    m = red[0];
    __syncthreads();

    float s = 0.0f;
#pragma unroll
    for (int i = 0; i < 8; i++) { v[i] = __expf(v[i] - m); s += v[i]; }
    s = wrSum(s);
    if (lane == 0) red[wid] = s;
    __syncthreads();
    if (tid < 32) {
        float t = (lane < 8) ? red[lane] : 0.0f;
        t = wrSum(t);
        if (lane == 0) red[0] = t;
    }
    __syncthreads();
    s = red[0];

    float r = scale / s;
    __nv_bfloat16* ob = S3 + row * 6144;
#pragma unroll
    for (int i = 0; i < 8; i++) {
        int idx = tid + i * 256;
        float x = v[i] * r;
        float hx = __bfloat162float(__float2bfloat16_rn(x));
        __nv_bfloat16 hb = __float2bfloat16_rn(hx);
        ob[idx]        = hb;
        ob[4096 + idx] = hb;
        ob[2048 + idx] = __float2bfloat16_rn(x - hx);
    }
}

// ---------------------------------------------------------------------------
extern "C" void kernel_launch(void* const* d_in, const int* in_sizes, int n_in,
                              void* d_out, int out_size)
{
    const float* x  = (const float*)d_in[0];
    const float* Wq = (const float*)d_in[1];
    const float* bq = (const float*)d_in[2];
    const float* Wk = (const float*)d_in[3];
    const float* bk = (const float*)d_in[4];
    const float* Wv = (const float*)d_in[5];
    const float* bv = (const float*)d_in[6];
    float* out = (float*)d_out;

    unsigned char* pool;
    cudaGetSymbolAddress((void**)&pool, g_pool);
    __nv_bfloat16* x3  = (__nv_bfloat16*)(pool + OFF_X3);
    __nv_bfloat16* Wq3 = (__nv_bfloat16*)(pool + OFF_WQ3);
    __nv_bfloat16* Wk3 = (__nv_bfloat16*)(pool + OFF_WK3);
    __nv_bfloat16* Wv3 = (__nv_bfloat16*)(pool + OFF_WV3);
    __nv_bfloat16* Q3  = (__nv_bfloat16*)(pool + OFF_Q3);
    __nv_bfloat16* K3b = (__nv_bfloat16*)(pool + OFF_K3);
    float*         Sm  = (float*)(pool + OFF_S);
    __nv_bfloat16* S3  = (__nv_bfloat16*)(pool + OFF_S3);
    __nv_bfloat16* Vt3 = (__nv_bfloat16*)(pool + OFF_VT3);

    cudaFuncSetAttribute(gemm_bf16<0, false>,
                         cudaFuncAttributeMaxDynamicSharedMemorySize, SMEM_TOT);
    cudaFuncSetAttribute(gemm_bf16<1, true>,
                         cudaFuncAttributeMaxDynamicSharedMemorySize, SMEM_TOT);
    cudaFuncSetAttribute(gemm_bf16<2, true>,
                         cudaFuncAttributeMaxDynamicSharedMemorySize, SMEM_TOT);

    dim3 blk(256);
    dim3 gblk(128);   // GEMM CTAs are 4 warps now

    // ---- 1. split raw inputs ----
    {
        long t4x = (long)BB * SS * DD / 4;
        split3<<<(unsigned)(t4x / 256), blk>>>(x, x3, 10, t4x, 2048, 1024);
        long t4w = (long)DD * DD / 4;
        split3<<<(unsigned)(t4w / 256), blk>>>(Wq, Wq3, 10, t4w, 1024, 2048);
        split3<<<(unsigned)(t4w / 256), blk>>>(Wk, Wk3, 10, t4w, 1024, 2048);
        split3<<<(unsigned)(t4w / 256), blk>>>(Wv, Wv3, 10, t4w, 1024, 2048);
    }

    // ---- 2. QKV projections (M=8192, N=1024, K3=3072) with fused splits ----
    {
        dim3 g(DD / 128, (BB * SS) / 128, 1);
        gemm_bf16<1, true><<<g, gblk, SMEM_TOT>>>(x3, Wq3, bq, Q3,
                                                  3 * DD, 0, 0, 0, 3 * DD, 2048, 1024);
        gemm_bf16<1, true><<<g, gblk, SMEM_TOT>>>(x3, Wk3, bk, K3b,
                                                  3 * DD, 0, 0, 0, 3 * DD, 1024, 2048);
        gemm_bf16<2, true><<<g, gblk, SMEM_TOT>>>(x3, Wv3, bv, Vt3,
                                                  3 * DD, 0, 0, 0, 0, 0, 0);
    }

    // ---- 3. scores: per-batch M=N=2048, K3=3072 -> Sm fp32 ----
    {
        dim3 g(SS / 128, SS / 128, BB);
        gemm_bf16<0, false><<<g, gblk, SMEM_TOT>>>(Q3, K3b, nullptr, Sm,
                                                   3 * DD,
                                                   (long)SS * 3 * DD, (long)SS * 3 * DD,
                                                   (long)SS * SS, SS, 0, 0);
    }

    // ---- 4. softmax + fused probs split ----
    softmax_split<<<BB * SS, blk>>>(Sm, S3, 0.03125f);

    // ---- 5. out: per-batch M=2048, N=1024, K3=6144 ----
    {
        dim3 g(DD / 128, SS / 128, BB);
        gemm_bf16<0, false><<<g, gblk, SMEM_TOT>>>(S3, Vt3, nullptr, out,
                                                   3 * SS,
                                                   (long)SS * 3 * SS, (long)DD * 3 * SS,
                                                   (long)SS * DD, DD, 0, 0);
    }
}

// round 8
// speedup vs baseline: 2.9407x; 1.0278x over previous
#include <cuda_runtime.h>
#include <cuda_bf16.h>
#include <cstdint>

// ============================================================================
// Self_Attention on GB300 (sm_103a), Round 8: bf16x3 mma.sync GEMMs.
//  - QKV projections merged into ONE launch (contiguous W3 pool, runtime
//    epilogue dispatch) to remove 2 launch tails.
//  - Launch order arranged so ncu (-s 5 -c 1) captures the scores GEMM.
//  - GEMM core identical to R7 (CTA 128x128, 4 warps, 64x64 warp tile, BK=64).
// Error-compensated bf16: A' = [Ah|Al|Ah], B' = [Bh|Bh|Bl], K' = 3K
// ============================================================================

#define BB 4
#define SS 2048
#define DD 1024

// ---------------------------------------------------------------------------
// Scratch pool  (W splits MUST stay contiguous: Wq3 | Wk3 | Wv3)
// ---------------------------------------------------------------------------
constexpr size_t SZ_X3  = (size_t)BB * SS * 3 * DD * 2;
constexpr size_t SZ_W3  = (size_t)DD * 3 * DD * 2;
constexpr size_t SZ_Q3  = (size_t)BB * SS * 3 * DD * 2;
constexpr size_t SZ_S   = (size_t)BB * SS * SS * 4;
constexpr size_t SZ_S3  = (size_t)BB * SS * 3 * SS * 2;
constexpr size_t SZ_VT3 = (size_t)BB * DD * 3 * SS * 2;

constexpr size_t OFF_X3  = 0;
constexpr size_t OFF_WQ3 = OFF_X3  + SZ_X3;
constexpr size_t OFF_WK3 = OFF_WQ3 + SZ_W3;
constexpr size_t OFF_WV3 = OFF_WK3 + SZ_W3;
constexpr size_t OFF_Q3  = OFF_WV3 + SZ_W3;
constexpr size_t OFF_K3  = OFF_Q3  + SZ_Q3;
constexpr size_t OFF_S   = OFF_K3  + SZ_Q3;
constexpr size_t OFF_S3  = OFF_S   + SZ_S;
constexpr size_t OFF_VT3 = OFF_S3  + SZ_S3;
constexpr size_t POOL_SZ = OFF_VT3 + SZ_VT3;

__device__ __align__(1024) static unsigned char g_pool[POOL_SZ];

// ---------------------------------------------------------------------------
// PTX helpers
// ---------------------------------------------------------------------------
static __device__ __forceinline__ uint32_t smem_u32(const void* p) {
    uint32_t a;
    asm("{ .reg .u64 t; cvta.to.shared.u64 t, %1; cvt.u32.u64 %0, t; }"
        : "=r"(a) : "l"(p));
    return a;
}
static __device__ __forceinline__ void cp16(uint32_t dst, const void* src) {
    asm volatile("cp.async.cg.shared.global [%0], [%1], 16;" :: "r"(dst), "l"(src));
}
static __device__ __forceinline__ void ldsm4(uint32_t& r0, uint32_t& r1,
                                             uint32_t& r2, uint32_t& r3, uint32_t addr) {
    asm volatile("ldmatrix.sync.aligned.m8n8.x4.shared.b16 {%0,%1,%2,%3}, [%4];"
                 : "=r"(r0), "=r"(r1), "=r"(r2), "=r"(r3) : "r"(addr));
}
static __device__ __forceinline__ void mma_bf16(float* d, const uint32_t* a,
                                                uint32_t b0, uint32_t b1) {
    asm volatile(
        "mma.sync.aligned.m16n8k16.row.col.f32.bf16.bf16.f32 "
        "{%0,%1,%2,%3}, {%4,%5,%6,%7}, {%8,%9}, {%0,%1,%2,%3};"
        : "+f"(d[0]), "+f"(d[1]), "+f"(d[2]), "+f"(d[3])
        : "r"(a[0]), "r"(a[1]), "r"(a[2]), "r"(a[3]), "r"(b0), "r"(b1));
}
static __device__ __forceinline__ uint32_t packbf(float x, float y) {
    __nv_bfloat162 h = __floats2bfloat162_rn(x, y);
    return *reinterpret_cast<uint32_t*>(&h);
}
static __device__ __forceinline__ void wsplit2(__nv_bfloat16* base, int offHi2,
                                               int offLo, float x, float y) {
    float hx = __bfloat162float(__float2bfloat16_rn(x));
    float hy = __bfloat162float(__float2bfloat16_rn(y));
    uint32_t hp = packbf(hx, hy);
    uint32_t lp = packbf(x - hx, y - hy);
    *(uint32_t*)(base)          = hp;
    *(uint32_t*)(base + offHi2) = hp;
    *(uint32_t*)(base + offLo)  = lp;
}

// ---------------------------------------------------------------------------
// Shared GEMM core: acc[4][8][4] = A[m0:m0+128, :K3] @ B[n0:n0+128, :K3]^T
// CTA 128x128, 4 warps (warp tile 64x64), BK=64, 3-stage cp.async pipeline.
// ---------------------------------------------------------------------------
#define STAGE_B 32768
#define SMEM_TOT (3 * STAGE_B)

static __device__ __forceinline__ void gemm_core(
    const __nv_bfloat16* __restrict__ A, const __nv_bfloat16* __restrict__ B,
    int K3, int m0, int n0, uint32_t sb, int tid, int lane, int wm, int wn,
    float acc[4][8][4])
{
    const int NC = K3 >> 6;

    auto prefetch = [&](int c) {
        const uint32_t st = sb + (c % 3) * STAGE_B;
        const __nv_bfloat16* Ab = A + (long)m0 * K3 + c * 64;
        const __nv_bfloat16* Bb = B + (long)n0 * K3 + c * 64;
#pragma unroll
        for (int i = 0; i < 8; i++) {
            int g = tid + i * 128;
            int r = g >> 3, c8 = g & 7;
            uint32_t off = (uint32_t)(r * 128 + ((c8 ^ (r & 7)) << 4));
            cp16(st + off,         Ab + (long)r * K3 + c8 * 8);
            cp16(st + 16384 + off, Bb + (long)r * K3 + c8 * 8);
        }
    };

    const int a_r  = wm * 64 + (lane & 15);
    const int a_c8 = lane >> 4;
    const uint32_t a_sw = (uint32_t)(a_r & 7);
    const int b_r  = wn * 64 + (lane & 7) + ((lane >> 4) << 3);
    const int b_c8 = (lane >> 3) & 1;
    const uint32_t b_sw = (uint32_t)(b_r & 7);

#pragma unroll
    for (int mi = 0; mi < 4; mi++)
#pragma unroll
        for (int nj = 0; nj < 8; nj++)
#pragma unroll
            for (int q = 0; q < 4; q++) acc[mi][nj][q] = 0.0f;

    prefetch(0);
    asm volatile("cp.async.commit_group;" ::: "memory");
    prefetch(1);
    asm volatile("cp.async.commit_group;" ::: "memory");

    for (int c = 0; c < NC; c++) {
        asm volatile("cp.async.wait_group 1;" ::: "memory");
        __syncthreads();
        if (c + 2 < NC) prefetch(c + 2);
        asm volatile("cp.async.commit_group;" ::: "memory");

        const uint32_t As = sb + (c % 3) * STAGE_B;
        const uint32_t Bs = As + 16384;
#pragma unroll
        for (int ks = 0; ks < 4; ks++) {
            uint32_t a[4][4];
#pragma unroll
            for (int mi = 0; mi < 4; mi++)
                ldsm4(a[mi][0], a[mi][1], a[mi][2], a[mi][3],
                      As + (uint32_t)((a_r + mi * 16) * 128)
                         + ((((uint32_t)(ks * 2 + a_c8)) ^ a_sw) << 4));
            uint32_t b[4][4];
#pragma unroll
            for (int pj = 0; pj < 4; pj++)
                ldsm4(b[pj][0], b[pj][1], b[pj][2], b[pj][3],
                      Bs + (uint32_t)((b_r + pj * 16) * 128)
                         + ((((uint32_t)(ks * 2 + b_c8)) ^ b_sw) << 4));
#pragma unroll
            for (int mi = 0; mi < 4; mi++)
#pragma unroll
                for (int nj = 0; nj < 8; nj++)
                    mma_bf16(acc[mi][nj], a[mi],
                             b[nj >> 1][(nj & 1) * 2], b[nj >> 1][(nj & 1) * 2 + 1]);
        }
        __syncthreads();
    }
}

// ---------------------------------------------------------------------------
// Kernel 1: merged QKV projection. A = x3 [8192, 3072], B = W3 [3072, 3072].
// blockIdx.x in [0,24): which = bx>>3 selects {Q, K, V} epilogue.
// ---------------------------------------------------------------------------
__global__ __launch_bounds__(128, 2)
void gemm_qkv(const __nv_bfloat16* __restrict__ A, const __nv_bfloat16* __restrict__ B,
              const float* __restrict__ bq, const float* __restrict__ bk,
              const float* __restrict__ bv,
              __nv_bfloat16* __restrict__ Q3, __nv_bfloat16* __restrict__ K3b,
              __nv_bfloat16* __restrict__ Vt3)
{
    extern __shared__ char smem[];
    const uint32_t sb = smem_u32(smem);
    const int tid = threadIdx.x;
    const int lane = tid & 31;
    const int wid = tid >> 5;
    const int wm = wid & 1;
    const int wn = wid >> 1;

    const int m0 = blockIdx.y * 128;
    const int n0 = blockIdx.x * 128;          // global over 3072 W-rows
    const int which = blockIdx.x >> 3;        // 0=Q, 1=K, 2=V
    const int ncol0 = n0 - which * 1024;      // local output col base

    float acc[4][8][4];
    gemm_core(A, B, 3 * DD, m0, n0, sb, tid, lane, wm, wn, acc);

    const float* bias = (which == 0) ? bq : (which == 1) ? bk : bv;
    const int tg = lane >> 2;
    const int tq = (lane & 3) * 2;
#pragma unroll
    for (int mi = 0; mi < 4; mi++) {
        const int row0 = m0 + wm * 64 + mi * 16 + tg;
        const int row1 = row0 + 8;
#pragma unroll
        for (int nj = 0; nj < 8; nj++) {
            const int col = ncol0 + wn * 64 + nj * 8 + tq;
            float bx = bias[col], by = bias[col + 1];
            float v0 = acc[mi][nj][0] + bx, v1 = acc[mi][nj][1] + by;
            float v2 = acc[mi][nj][2] + bx, v3 = acc[mi][nj][3] + by;
            if (which == 0) {
                wsplit2(Q3 + (long)row0 * 3072 + col, 2048, 1024, v0, v1);
                wsplit2(Q3 + (long)row1 * 3072 + col, 2048, 1024, v2, v3);
            } else if (which == 1) {
                wsplit2(K3b + (long)row0 * 3072 + col, 1024, 2048, v0, v1);
                wsplit2(K3b + (long)row1 * 3072 + col, 1024, 2048, v2, v3);
            } else {
                const float vv[4] = {v0, v1, v2, v3};
                const int rr[2] = {row0, row1};
#pragma unroll
                for (int h = 0; h < 2; h++) {
                    const int row = rr[h];
                    __nv_bfloat16* b0 =
                        Vt3 + ((long)(row >> 11) * 1024 + col) * 6144 + (row & 2047);
#pragma unroll
                    for (int e = 0; e < 2; e++) {
                        float x = vv[h * 2 + e];
                        float hx = __bfloat162float(__float2bfloat16_rn(x));
                        __nv_bfloat16* bp = b0 + (long)e * 6144;
                        __nv_bfloat16 hb = __float2bfloat16_rn(hx);
                        bp[0]    = hb;
                        bp[2048] = hb;
                        bp[4096] = __float2bfloat16_rn(x - hx);
                    }
                }
            }
        }
    }
}

// ---------------------------------------------------------------------------
// Kernel 2: plain NT GEMM, fp32 output (scores and out). Batched via z.
// ---------------------------------------------------------------------------
__global__ __launch_bounds__(128, 2)
void gemm_f32(const __nv_bfloat16* __restrict__ A, const __nv_bfloat16* __restrict__ B,
              float* __restrict__ C, int K3, long sA, long sB, long sC, int ldc)
{
    extern __shared__ char smem[];
    const uint32_t sb = smem_u32(smem);
    const int tid = threadIdx.x;
    const int lane = tid & 31;
    const int wid = tid >> 5;
    const int wm = wid & 1;
    const int wn = wid >> 1;

    const long z = blockIdx.z;
    A += z * sA; B += z * sB; C += z * sC;
    const int m0 = blockIdx.y * 128;
    const int n0 = blockIdx.x * 128;

    float acc[4][8][4];
    gemm_core(A, B, K3, m0, n0, sb, tid, lane, wm, wn, acc);

    const int tg = lane >> 2;
    const int tq = (lane & 3) * 2;
#pragma unroll
    for (int mi = 0; mi < 4; mi++) {
        const int row0 = m0 + wm * 64 + mi * 16 + tg;
        const int row1 = row0 + 8;
#pragma unroll
        for (int nj = 0; nj < 8; nj++) {
            const int col = n0 + wn * 64 + nj * 8 + tq;
            *(float2*)(C + (long)row0 * ldc + col) =
                make_float2(acc[mi][nj][0], acc[mi][nj][1]);
            *(float2*)(C + (long)row1 * ldc + col) =
                make_float2(acc[mi][nj][2], acc[mi][nj][3]);
        }
    }
}

// ---------------------------------------------------------------------------
// fp32 -> bf16 triple split (raw inputs x / W only)
// ---------------------------------------------------------------------------
__global__ __launch_bounds__(256)
void split3(const float* __restrict__ in, __nv_bfloat16* __restrict__ out,
            int kshift, long total4, int offHi2, int offLo)
{
    long i4 = (long)blockIdx.x * 256 + threadIdx.x;
    if (i4 >= total4) return;
    long e = i4 << 2;
    long row = e >> kshift;
    int k = (int)(e & ((1L << kshift) - 1));
    float4 v = ((const float4*)in)[i4];

    float hx = __bfloat162float(__float2bfloat16_rn(v.x));
    float hy = __bfloat162float(__float2bfloat16_rn(v.y));
    float hz = __bfloat162float(__float2bfloat16_rn(v.z));
    float hw = __bfloat162float(__float2bfloat16_rn(v.w));
    uint2 hp = make_uint2(packbf(hx, hy), packbf(hz, hw));
    uint2 lp = make_uint2(packbf(v.x - hx, v.y - hy), packbf(v.z - hz, v.w - hw));

    __nv_bfloat16* ob = out + row * 3 * (1L << kshift);
    *(uint2*)(ob + k)          = hp;
    *(uint2*)(ob + offHi2 + k) = hp;
    *(uint2*)(ob + offLo + k)  = lp;
}

// ---------------------------------------------------------------------------
// softmax + fused probs split
// ---------------------------------------------------------------------------
static __inline__ __device__ float wrMax(float v) {
#pragma unroll
    for (int o = 16; o > 0; o >>= 1) v = fmaxf(v, __shfl_xor_sync(0xffffffffu, v, o));
    return v;
}
static __inline__ __device__ float wrSum(float v) {
#pragma unroll
    for (int o = 16; o > 0; o >>= 1) v += __shfl_xor_sync(0xffffffffu, v, o);
    return v;
}

__global__ __launch_bounds__(256)
void softmax_split(const float* __restrict__ Sm, __nv_bfloat16* __restrict__ S3,
                   float scale)
{
    __shared__ float red[8];
    const long row = blockIdx.x;
    const float* p = Sm + row * 2048;
    const int tid = threadIdx.x;
    const int lane = tid & 31;
    const int wid = tid >> 5;

    float v[8];
#pragma unroll
    for (int i = 0; i < 8; i++) v[i] = p[tid + i * 256];

    float m = -1e30f;
#pragma unroll
    for (int i = 0; i < 8; i++) m = fmaxf(m, v[i]);
    m = wrMax(m);
    if (lane == 0) red[wid] = m;
    __syncthreads();
    if (tid < 32) {
        float t = (lane < 8) ? red[lane] : -1e30f;
        t = wrMax(t);
        if (lane == 0) red[0] = t;
    }
    __syncthreads();
    m = red[0];
    __syncthreads();

    float s = 0.0f;
#pragma unroll
    for (int i = 0; i < 8; i++) { v[i] = __expf(v[i] - m); s += v[i]; }
    s = wrSum(s);
    if (lane == 0) red[wid] = s;
    __syncthreads();
    if (tid < 32) {
        float t = (lane < 8) ? red[lane] : 0.0f;
        t = wrSum(t);
        if (lane == 0) red[0] = t;
    }
    __syncthreads();
    s = red[0];

    float r = scale / s;
    __nv_bfloat16* ob = S3 + row * 6144;
#pragma unroll
    for (int i = 0; i < 8; i++) {
        int idx = tid + i * 256;
        float x = v[i] * r;
        float hx = __bfloat162float(__float2bfloat16_rn(x));
        __nv_bfloat16 hb = __float2bfloat16_rn(hx);
        ob[idx]        = hb;
        ob[4096 + idx] = hb;
        ob[2048 + idx] = __float2bfloat16_rn(x - hx);
    }
}

// ---------------------------------------------------------------------------
extern "C" void kernel_launch(void* const* d_in, const int* in_sizes, int n_in,
                              void* d_out, int out_size)
{
    const float* x  = (const float*)d_in[0];
    const float* Wq = (const float*)d_in[1];
    const float* bq = (const float*)d_in[2];
    const float* Wk = (const float*)d_in[3];
    const float* bk = (const float*)d_in[4];
    const float* Wv = (const float*)d_in[5];
    const float* bv = (const float*)d_in[6];
    float* out = (float*)d_out;

    unsigned char* pool;
    cudaGetSymbolAddress((void**)&pool, g_pool);
    __nv_bfloat16* x3  = (__nv_bfloat16*)(pool + OFF_X3);
    __nv_bfloat16* W3  = (__nv_bfloat16*)(pool + OFF_WQ3);   // Wq3|Wk3|Wv3 contiguous
    __nv_bfloat16* Wq3 = (__nv_bfloat16*)(pool + OFF_WQ3);
    __nv_bfloat16* Wk3 = (__nv_bfloat16*)(pool + OFF_WK3);
    __nv_bfloat16* Wv3 = (__nv_bfloat16*)(pool + OFF_WV3);
    __nv_bfloat16* Q3  = (__nv_bfloat16*)(pool + OFF_Q3);
    __nv_bfloat16* K3b = (__nv_bfloat16*)(pool + OFF_K3);
    float*         Sm  = (float*)(pool + OFF_S);
    __nv_bfloat16* S3  = (__nv_bfloat16*)(pool + OFF_S3);
    __nv_bfloat16* Vt3 = (__nv_bfloat16*)(pool + OFF_VT3);

    cudaFuncSetAttribute(gemm_qkv, cudaFuncAttributeMaxDynamicSharedMemorySize, SMEM_TOT);
    cudaFuncSetAttribute(gemm_f32, cudaFuncAttributeMaxDynamicSharedMemorySize, SMEM_TOT);

    dim3 blk(256);
    dim3 gblk(128);

    // ---- launches 0-3: input splits (order fixed so ncu -s5 hits scores) ----
    {
        long t4x = (long)BB * SS * DD / 4;
        split3<<<(unsigned)(t4x / 256), blk>>>(x, x3, 10, t4x, 2048, 1024);
        long t4w = (long)DD * DD / 4;
        split3<<<(unsigned)(t4w / 256), blk>>>(Wq, Wq3, 10, t4w, 1024, 2048);
        split3<<<(unsigned)(t4w / 256), blk>>>(Wk, Wk3, 10, t4w, 1024, 2048);
        split3<<<(unsigned)(t4w / 256), blk>>>(Wv, Wv3, 10, t4w, 1024, 2048);
    }

    // ---- launch 4: merged QKV projection (M=8192, N=3*1024, K3=3072) ----
    {
        dim3 g(3 * DD / 128, (BB * SS) / 128, 1);
        gemm_qkv<<<g, gblk, SMEM_TOT>>>(x3, W3, bq, bk, bv, Q3, K3b, Vt3);
    }

    // ---- launch 5: scores (per-batch M=N=2048, K3=3072) -> Sm fp32 ----
    {
        dim3 g(SS / 128, SS / 128, BB);
        gemm_f32<<<g, gblk, SMEM_TOT>>>(Q3, K3b, Sm, 3 * DD,
                                        (long)SS * 3 * DD, (long)SS * 3 * DD,
                                        (long)SS * SS, SS);
    }

    // ---- launch 6: softmax + fused probs split ----
    softmax_split<<<BB * SS, blk>>>(Sm, S3, 0.03125f);

    // ---- launch 7: out (per-batch M=2048, N=1024, K3=6144) ----
    {
        dim3 g(DD / 128, SS / 128, BB);
        gemm_f32<<<g, gblk, SMEM_TOT>>>(S3, Vt3, out, 3 * SS,
                                        (long)SS * 3 * SS, (long)DD * 3 * SS,
                                        (long)SS * DD, DD);
    }
}